// round 1
// baseline (speedup 1.0000x reference)
#include <cuda_runtime.h>
#include <math.h>

// Problem constants
#define TQ    2048
#define TKV   2048
#define CEMB  1024
#define NHEAD 16
#define DH    64
#define BATCH 2

// Scratch (no cudaMalloc allowed): Q [4096,1024], KV [4096,2048], Y [4096,1024]
__device__ float g_Q [4096u * 1024u];
__device__ float g_KV[4096u * 2048u];
__device__ float g_Y [4096u * 1024u];

// ---------------------------------------------------------------------------
// SGEMM: C[M,N] = A[M,K] * B[K,N], row-major, all dims multiples of 128.
// Classic 128x128x8 tile, 256 threads, 8x8 per-thread microtile, float4 I/O.
// ---------------------------------------------------------------------------
__global__ __launch_bounds__(256, 2)
void sgemm128(const float* __restrict__ A, const float* __restrict__ B,
              float* __restrict__ C, int M, int N, int K)
{
    __shared__ float As[8][128];   // transposed A tile: As[k][m]
    __shared__ float Bs[8][128];   // Bs[k][n]

    const int tid  = threadIdx.x;
    const int tcol = tid & 15;     // 0..15  -> columns tcol*8..+8
    const int trow = tid >> 4;     // 0..15  -> rows    trow*8..+8

    const float* Ab = A + (size_t)blockIdx.y * 128 * K;
    const float* Bb = B + (size_t)blockIdx.x * 128;
    float*       Cb = C + (size_t)blockIdx.y * 128 * N + (size_t)blockIdx.x * 128;

    const int aRow = tid >> 1;          // 0..127
    const int aCol = (tid & 1) * 4;     // 0 or 4
    const int bRow = tid >> 5;          // 0..7
    const int bCol = (tid & 31) * 4;    // 0..124

    float acc[8][8];
    #pragma unroll
    for (int i = 0; i < 8; i++)
        #pragma unroll
        for (int j = 0; j < 8; j++)
            acc[i][j] = 0.0f;

    for (int k0 = 0; k0 < K; k0 += 8) {
        // Load A tile (128x8) and scatter transposed into As
        float4 av = *(const float4*)(Ab + (size_t)aRow * K + k0 + aCol);
        As[aCol + 0][aRow] = av.x;
        As[aCol + 1][aRow] = av.y;
        As[aCol + 2][aRow] = av.z;
        As[aCol + 3][aRow] = av.w;
        // Load B tile (8x128)
        *(float4*)&Bs[bRow][bCol] = *(const float4*)(Bb + (size_t)(k0 + bRow) * N + bCol);
        __syncthreads();

        #pragma unroll
        for (int k = 0; k < 8; k++) {
            float rm[8], rn[8];
            *(float4*)(rm)     = *(float4*)&As[k][trow * 8];
            *(float4*)(rm + 4) = *(float4*)&As[k][trow * 8 + 4];
            *(float4*)(rn)     = *(float4*)&Bs[k][tcol * 8];
            *(float4*)(rn + 4) = *(float4*)&Bs[k][tcol * 8 + 4];
            #pragma unroll
            for (int i = 0; i < 8; i++)
                #pragma unroll
                for (int j = 0; j < 8; j++)
                    acc[i][j] = fmaf(rm[i], rn[j], acc[i][j]);
        }
        __syncthreads();
    }

    #pragma unroll
    for (int i = 0; i < 8; i++) {
        float* crow = Cb + (size_t)(trow * 8 + i) * N + tcol * 8;
        *(float4*)(crow)     = make_float4(acc[i][0], acc[i][1], acc[i][2], acc[i][3]);
        *(float4*)(crow + 4) = make_float4(acc[i][4], acc[i][5], acc[i][6], acc[i][7]);
    }
}

// ---------------------------------------------------------------------------
// Fused attention (flash style), fp32.
//   grid = (TQ/64, NHEAD, BATCH), block = 256
//   Q tile 64 rows, KV tile 32 rows, Dh = 64.
//   scores = (q . k) * 8.0  (reference divides by Dh^-0.5)
// Thread roles:
//   r = tid>>2 (0..63): this thread's O row; g = tid&3: its 16-wide d / j group.
//   Threads 0..63 additionally own softmax state (m, l) for row == tid.
// ---------------------------------------------------------------------------
__global__ __launch_bounds__(256, 2)
void attn_kernel(const float* __restrict__ Q, const float* __restrict__ KV,
                 float* __restrict__ Y)
{
    __shared__ float Qs[64][68];   // 17408 B
    __shared__ float Ks[32][68];   //  8704 B
    __shared__ float Vs[32][68];   //  8704 B
    __shared__ float Ps[64][36];   //  9216 B
    __shared__ float srow[64];     //   256 B   (total 44288 B)

    const int tid = threadIdx.x;
    const int b   = blockIdx.z;
    const int h   = blockIdx.y;
    const int q0  = blockIdx.x * 64;

    const float* Qb = Q  + ((size_t)b * TQ  + q0) * CEMB + h * DH;
    const float* Kb = KV + ((size_t)b * TKV) * (2 * CEMB) + h * DH;
    const float* Vb = Kb + CEMB;

    // Load Q tile: 64 x 64 floats = 1024 float4
    for (int i = tid; i < 64 * 16; i += 256) {
        int r  = i >> 4;
        int c4 = (i & 15) * 4;
        *(float4*)&Qs[r][c4] = *(const float4*)(Qb + (size_t)r * CEMB + c4);
    }

    const int r = tid >> 2;   // O-row
    const int g = tid & 3;    // group

    float m = -1e30f, l = 0.0f;      // softmax state for row==tid (tid<64)
    float4 o4[4];
    #pragma unroll
    for (int i = 0; i < 4; i++) o4[i] = make_float4(0.f, 0.f, 0.f, 0.f);

    __syncthreads();

    for (int t0 = 0; t0 < TKV; t0 += 32) {
        // Load K and V tiles: 32 x 16 float4 each
        for (int i = tid; i < 512; i += 256) {
            int rr = i >> 4;
            int c4 = (i & 15) * 4;
            *(float4*)&Ks[rr][c4] = *(const float4*)(Kb + (size_t)(t0 + rr) * (2 * CEMB) + c4);
            *(float4*)&Vs[rr][c4] = *(const float4*)(Vb + (size_t)(t0 + rr) * (2 * CEMB) + c4);
        }
        __syncthreads();

        // S[r][g + 4*jj] for jj = 0..7
        float acc[8];
        #pragma unroll
        for (int jj = 0; jj < 8; jj++) acc[jj] = 0.0f;
        #pragma unroll 4
        for (int d4 = 0; d4 < 16; d4++) {
            float4 qv = *(float4*)&Qs[r][d4 * 4];
            #pragma unroll
            for (int jj = 0; jj < 8; jj++) {
                float4 kv = *(float4*)&Ks[g + jj * 4][d4 * 4];
                acc[jj] += qv.x * kv.x + qv.y * kv.y + qv.z * kv.z + qv.w * kv.w;
            }
        }
        #pragma unroll
        for (int jj = 0; jj < 8; jj++)
            Ps[r][g + jj * 4] = acc[jj] * 8.0f;
        __syncthreads();

        // Online softmax: thread tid < 64 owns row tid
        if (tid < 64) {
            float mt = m;
            #pragma unroll 8
            for (int j = 0; j < 32; j++) mt = fmaxf(mt, Ps[tid][j]);
            float sc = __expf(m - mt);
            float ls = 0.0f;
            #pragma unroll 8
            for (int j = 0; j < 32; j++) {
                float p = __expf(Ps[tid][j] - mt);
                Ps[tid][j] = p;
                ls += p;
            }
            l = l * sc + ls;
            m = mt;
            srow[tid] = sc;
        }
        __syncthreads();

        // Rescale O and accumulate P @ V
        float sc = srow[r];
        #pragma unroll
        for (int i = 0; i < 4; i++) {
            o4[i].x *= sc; o4[i].y *= sc; o4[i].z *= sc; o4[i].w *= sc;
        }
        #pragma unroll 8
        for (int j = 0; j < 32; j++) {
            float p = Ps[r][j];
            #pragma unroll
            for (int i4 = 0; i4 < 4; i4++) {
                float4 vv = *(float4*)&Vs[j][g * 16 + i4 * 4];
                o4[i4].x = fmaf(p, vv.x, o4[i4].x);
                o4[i4].y = fmaf(p, vv.y, o4[i4].y);
                o4[i4].z = fmaf(p, vv.z, o4[i4].z);
                o4[i4].w = fmaf(p, vv.w, o4[i4].w);
            }
        }
        __syncthreads();   // protect Ks/Vs/Ps before next tile's loads
    }

    // Finalize: divide by l and write Y
    if (tid < 64) srow[tid] = 1.0f / l;
    __syncthreads();
    float inv = srow[r];
    float* Yb = Y + ((size_t)b * TQ + q0 + r) * CEMB + h * DH + g * 16;
    #pragma unroll
    for (int i4 = 0; i4 < 4; i4++) {
        *(float4*)(Yb + i4 * 4) = make_float4(o4[i4].x * inv, o4[i4].y * inv,
                                              o4[i4].z * inv, o4[i4].w * inv);
    }
}

// ---------------------------------------------------------------------------
extern "C" void kernel_launch(void* const* d_in, const int* in_sizes, int n_in,
                              void* d_out, int out_size)
{
    const float* x_q    = (const float*)d_in[0];   // [2,2048,1024]
    const float* x_kv   = (const float*)d_in[1];   // [2,2048,1024]
    const float* W_q    = (const float*)d_in[2];   // [1024,1024]
    const float* W_kv   = (const float*)d_in[3];   // [1024,2048]
    const float* W_proj = (const float*)d_in[4];   // [1024,1024]
    float*       out    = (float*)d_out;           // [2,2048,1024]

    float *Qp = nullptr, *KVp = nullptr, *Yp = nullptr;
    cudaGetSymbolAddress((void**)&Qp,  g_Q);
    cudaGetSymbolAddress((void**)&KVp, g_KV);
    cudaGetSymbolAddress((void**)&Yp,  g_Y);

    const int M = BATCH * TQ;    // 4096

    // Q = x_q @ W_q : [4096,1024]
    sgemm128<<<dim3(CEMB / 128, M / 128), 256>>>(x_q, W_q, Qp, M, CEMB, CEMB);
    // KV = x_kv @ W_kv : [4096,2048]
    sgemm128<<<dim3(2 * CEMB / 128, M / 128), 256>>>(x_kv, W_kv, KVp, M, 2 * CEMB, CEMB);
    // Attention -> Y : [4096,1024]
    attn_kernel<<<dim3(TQ / 64, NHEAD, BATCH), 256>>>(Qp, KVp, Yp);
    // out = Y @ W_proj : [4096,1024]
    sgemm128<<<dim3(CEMB / 128, M / 128), 256>>>(Yp, W_proj, out, M, CEMB, CEMB);
}